// round 16
// baseline (speedup 1.0000x reference)
#include <cuda_runtime.h>
#include <cuda_fp16.h>
#include <math.h>

// Problem constants (fixed by the dataset)
#define NGB 16          // graphs
#define NN  2048        // nodes per graph
#define NTT 32768       // total nodes
#define CIN 64
#define HID 128
#define KC  32
#define EDG 524288      // total edges
#define EPG 32768       // edges per graph
#define GN_EPS 1e-5f
#define SELU_SCALE 1.0507009873554805f
#define SELU_ALPHA 1.6732632423543772f

// ---------------- scratch (device globals; no allocation allowed) ----------------
__device__ __align__(16) float g_sumP[128 * CIN];    // per (g,part) partial sums
__device__ __align__(16) float g_sumsqP[128 * CIN];
__device__ __align__(16) float g_gnA[NGB * CIN];     // alpha*mean
__device__ __align__(16) float g_gnS[NGB * CIN];     // gw * rsqrt(var+eps)
__device__ int   g_indeg[NTT];
__device__ int   g_odeg[NTT];
__device__ int   g_rowptr[NTT];
__device__ int   g_cursor[NTT];
__device__ int   g_csrsrc[EDG];
__device__ __align__(16) float g_dinv[NTT];
__device__ __align__(16) __half g_hwh[NTT * HID];    // fp16: dinv*(graphnorm(x)@w1)
__device__ __align__(16) __half g_sh[NTT * KC];      // fp16 copy of s (for trace)
__device__ __align__(16) float g_xd[NTT * HID];
__device__ __align__(16) float g_s[NTT * KC];
__device__ float g_tr[NGB];
__device__ __align__(16) float g_outP[NGB * 16 * KC * HID]; // pool partials, slot=(g*8+chunk)*2+ns
__device__ __align__(16) float g_ssP[NGB * 8 * KC * KC];
__device__ __align__(16) float g_caP[NGB * 8 * KC];
__device__ __align__(16) float g_csP[NGB * 8 * KC];

__device__ __forceinline__ float selu_f(float v) {
    return v > 0.f ? SELU_SCALE * v : SELU_SCALE * SELU_ALPHA * (expf(v) - 1.f);
}

// ---------------- kernels ----------------

// zero only the atomic-receiving degree arrays.  grid 64 x 256 (int4).
__global__ void __launch_bounds__(256) zero_k() {
    int i = blockIdx.x * 256 + threadIdx.x;       // 0..16383
    if (i < 8192) ((int4*)g_indeg)[i] = make_int4(0, 0, 0, 0);
    else          ((int4*)g_odeg)[i - 8192] = make_int4(0, 0, 0, 0);
}

// blocks<128: GraphNorm moment partials (no atomics).  blocks>=128: degree hist.
__global__ void __launch_bounds__(512) stats_hist_k(const float* __restrict__ x,
                                                    const int* __restrict__ ei) {
    int b = blockIdx.x, t = threadIdx.x;
    if (b < 128) {
        int g = b >> 3, part = b & 7;
        int c = t & 63, rp = t >> 6;
        float s = 0.f, q = 0.f;
        const float* xb = x + (size_t)g * NN * CIN;
        int r0 = part * 256;
        for (int r = r0 + rp; r < r0 + 256; r += 8) {
            float v = xb[r * CIN + c];
            s += v; q += v * v;
        }
        __shared__ float sh[2][8][64];
        sh[0][rp][c] = s; sh[1][rp][c] = q;
        __syncthreads();
        if (t < 64) {
            float ss = 0.f, qq = 0.f;
#pragma unroll
            for (int i = 0; i < 8; i++) { ss += sh[0][i][t]; qq += sh[1][i][t]; }
            g_sumP[b * 64 + t] = ss;
            g_sumsqP[b * 64 + t] = qq;
        }
    } else {
        int e = (b - 128) * 512 + t;    // 1024 blocks x 512 = EDG
        atomicAdd(&g_indeg[ei[EDG + e]], 1);
        atomicAdd(&g_odeg[ei[e]], 1);
    }
}

// per-graph: finalize GN coefficients + exclusive scan of indeg -> rowptr/cursor/dinv
// grid = 16 blocks x 1024.
__global__ void __launch_bounds__(1024) prep2_k(const float* __restrict__ gw,
                                                const float* __restrict__ gms) {
    __shared__ int wsum[32];
    int g = blockIdx.x, t = threadIdx.x;

    if (t < 64) {
        float ss = 0.f, qq = 0.f;
#pragma unroll
        for (int p = 0; p < 8; p++) {
            ss += g_sumP[(g * 8 + p) * 64 + t];
            qq += g_sumsqP[(g * 8 + p) * 64 + t];
        }
        float mean = ss * (1.f / NN);
        float alpha = gms[t];
        float var = qq * (1.f / NN) - (2.f * alpha - alpha * alpha) * mean * mean;
        g_gnS[g * 64 + t] = gw[t] * rsqrtf(var + GN_EPS);
        g_gnA[g * 64 + t] = alpha * mean;
    }
    if (t == 0) g_tr[g] = 0.f;

    int n0 = g * NN + 2 * t;
    int v0 = g_indeg[n0], v1 = g_indeg[n0 + 1];
    int ps = v0 + v1;
    int lane = t & 31, wp = t >> 5;
    int xs = ps;
#pragma unroll
    for (int o = 1; o < 32; o <<= 1) {
        int y = __shfl_up_sync(0xffffffffu, xs, o);
        if (lane >= o) xs += y;
    }
    if (lane == 31) wsum[wp] = xs;
    __syncthreads();
    if (t < 32) {
        int v = wsum[t];
        int y = v;
#pragma unroll
        for (int o = 1; o < 32; o <<= 1) {
            int z = __shfl_up_sync(0xffffffffu, y, o);
            if (t >= o) y += z;
        }
        wsum[t] = y - v;
    }
    __syncthreads();
    int ex = wsum[wp] + xs - ps;
    int ebase = g * EPG;
    g_rowptr[n0] = ebase + ex;
    g_rowptr[n0 + 1] = ebase + ex + v0;
    g_cursor[n0] = ebase + ex;
    g_cursor[n0 + 1] = ebase + ex + v0;
    g_dinv[n0] = rsqrtf((float)v0 + 1.f);
    g_dinv[n0 + 1] = rsqrtf((float)v1 + 1.f);
}

// CSR scatter, zero smem, full occupancy, ILP 4.  grid 512 x 256.
__global__ void __launch_bounds__(256) scatter_k(const int* __restrict__ ei) {
    int e0 = (blockIdx.x * 256 + threadIdx.x) * 4;
    int4 s4 = *(const int4*)(ei + e0);
    int4 d4 = *(const int4*)(ei + EDG + e0);
    int p0 = atomicAdd(&g_cursor[d4.x], 1);
    int p1 = atomicAdd(&g_cursor[d4.y], 1);
    int p2 = atomicAdd(&g_cursor[d4.z], 1);
    int p3 = atomicAdd(&g_cursor[d4.w], 1);
    g_csrsrc[p0] = s4.x;
    g_csrsrc[p1] = s4.y;
    g_csrsrc[p2] = s4.z;
    g_csrsrc[p3] = s4.w;
}

// fused GraphNorm + GEMM1 -> fp16.  256 threads: col = t&127, row-group = t>>7.
// grid 512, 4 tiles of 16 rows per block.
__global__ void __launch_bounds__(256) gemm1h_k(
    const float* __restrict__ x, const float* __restrict__ gb,
    const float* __restrict__ w1)
{
    __shared__ float w1t[HID * (CIN + 4)];   // 34 KB, w1t[col][c] = w1[c][col]
    __shared__ float A[CIN], S[CIN], Bc[CIN];
    __shared__ float hsh[16][CIN];           // 4 KB
    __shared__ float dvs[16];
    int t = threadIdx.x;
    int col = t & 127, rg = t >> 7;          // rg in {0,1}

    // load w1 transposed: thread pair (col, half) loads 32 channels
    for (int c = rg * 32; c < rg * 32 + 32; c++)
        w1t[col * (CIN + 4) + c] = w1[c * HID + col];
    if (t < 64) Bc[t] = gb[t];

    for (int tile = blockIdx.x; tile < NTT / 16; tile += 512) {
        int row0 = tile * 16;
        int g = row0 >> 11;
        __syncthreads();
        if (t < 64) { A[t] = g_gnA[g * 64 + t]; S[t] = g_gnS[g * 64 + t]; }
        if (t < 16) dvs[t] = g_dinv[row0 + t];
        __syncthreads();
#pragma unroll
        for (int i = 0; i < 4; i++) {
            int idx = t + i * 256;
            int rr = idx >> 6, c = idx & 63;
            float v = x[(size_t)(row0 + rr) * CIN + c];
            hsh[rr][c] = (v - A[c]) * S[c] + Bc[c];
        }
        __syncthreads();
        float acc[8];
#pragma unroll
        for (int r = 0; r < 8; r++) acc[r] = 0.f;
#pragma unroll
        for (int c = 0; c < CIN; c += 4) {
            float4 w = *(const float4*)&w1t[col * (CIN + 4) + c];
#pragma unroll
            for (int r = 0; r < 8; r++) {
                float4 h = *(const float4*)&hsh[rg * 8 + r][c];
                acc[r] += w.x * h.x + w.y * h.y + w.z * h.z + w.w * h.w;
            }
        }
#pragma unroll
        for (int r = 0; r < 8; r++)
            g_hwh[(size_t)(row0 + rg * 8 + r) * HID + col] =
                __float2half(acc[r] * dvs[rg * 8 + r]);
    }
}

__device__ __forceinline__ void acc_h4(float4& acc, uint2 u) {
    __half2 ha = *(__half2*)&u.x, hb = *(__half2*)&u.y;
    float2 f0 = __half22float2(ha), f1 = __half22float2(hb);
    acc.x += f0.x; acc.y += f0.y; acc.z += f1.x; acc.w += f1.y;
}

// fused CSR gather (fp16 rows, MLP 8) + SELU + softmax(xd @ w2 + b2).
// one warp per dst row; 1024 blocks x 8 warps, grid-stride (4 sweeps).
__global__ void __launch_bounds__(256) gxsh_k(
    const float* __restrict__ b1, const float* __restrict__ w2,
    const float* __restrict__ b2, float* __restrict__ s_out)
{
    __shared__ float w2t[KC * (HID + 4)];   // ~17 KB
    __shared__ float xds[8][HID];
    int t = threadIdx.x, wp = t >> 5, l = t & 31;
    for (int idx = t; idx < KC * HID; idx += 256) {
        int j = idx >> 5, ll = idx & 31;
        w2t[ll * (HID + 4) + j] = w2[idx];
    }
    __syncthreads();

    float4 bv = ((const float4*)b1)[l];
    float bz = b2[l];
    const uint2* hwp = (const uint2*)g_hwh;   // row stride = 32 uint2 (256B)

    for (int row = blockIdx.x * 8 + wp; row < NTT; row += 8192) {
        float dd = g_dinv[row];
        float4 acc = make_float4(0.f, 0.f, 0.f, 0.f);
        acc_h4(acc, hwp[(size_t)row * 32 + l]);      // self-loop term
        int start = g_rowptr[row], cnt = g_indeg[row];
        for (int base = 0; base < cnt; base += 32) {
            int n = min(32, cnt - base);
            int idx_l = (base + l < cnt) ? g_csrsrc[start + base + l] : 0;
            int i = 0;
            for (; i + 8 <= n; i += 8) {
                int sd[8]; uint2 uu[8];
#pragma unroll
                for (int q = 0; q < 8; q++) sd[q] = __shfl_sync(0xffffffffu, idx_l, i + q);
#pragma unroll
                for (int q = 0; q < 8; q++) uu[q] = hwp[(size_t)sd[q] * 32 + l];
#pragma unroll
                for (int q = 0; q < 8; q++) acc_h4(acc, uu[q]);
            }
            for (; i < n; i++) {
                int s = __shfl_sync(0xffffffffu, idx_l, i);
                acc_h4(acc, hwp[(size_t)s * 32 + l]);
            }
        }
        float4 xv;
        xv.x = selu_f(acc.x * dd + bv.x);
        xv.y = selu_f(acc.y * dd + bv.y);
        xv.z = selu_f(acc.z * dd + bv.z);
        xv.w = selu_f(acc.w * dd + bv.w);
        ((float4*)g_xd)[(size_t)row * 32 + l] = xv;
        *((float4*)&xds[wp][l * 4]) = xv;
        __syncwarp();

        float z = bz;
#pragma unroll
        for (int j = 0; j < HID; j += 4) {
            float4 xj = *(const float4*)&xds[wp][j];
            float4 wj = *(const float4*)&w2t[l * (HID + 4) + j];
            z += xj.x * wj.x + xj.y * wj.y + xj.z * wj.z + xj.w * wj.w;
        }
        float mx = z;
#pragma unroll
        for (int o = 16; o; o >>= 1) mx = fmaxf(mx, __shfl_xor_sync(0xffffffffu, mx, o));
        float ez = expf(z - mx);
        float sm = ez;
#pragma unroll
        for (int o = 16; o; o >>= 1) sm += __shfl_xor_sync(0xffffffffu, sm, o);
        float sv = ez / sm;
        s_out[(size_t)row * KC + l] = sv;
        g_s[(size_t)row * KC + l] = sv;
        g_sh[(size_t)row * KC + l] = __float2half(sv);
        __syncwarp();
    }
}

// blocks<128: register-tiled pooled reductions (partials, no atomics; one slot per ns).
// blocks>=128: CSR trace over fp16 s (MLP 8).
__global__ void __launch_bounds__(256) pool_trace_k() {
    __shared__ float xsh[64 * 128];   // 32 KB
    __shared__ float ssh[64 * 32];    // 8 KB
    __shared__ float dsh[64];
    int t = threadIdx.x;

    if (blockIdx.x < 128) {
        int g = blockIdx.x >> 3;
        int chunk = blockIdx.x & 7;
        int base = g * NN + chunk * 256;
        int ns = t >> 7;
        int tile = t & 127;
        int kb = tile >> 5;
        int fb = tile & 31;
        int k1 = t >> 3;
        int k2g = t & 7;

        float acc[8][4];
#pragma unroll
        for (int i = 0; i < 8; i++)
#pragma unroll
            for (int j = 0; j < 4; j++) acc[i][j] = 0.f;
        float4 ssacc = make_float4(0.f, 0.f, 0.f, 0.f);
        float caacc = 0.f, csacc = 0.f;

        float4* xsh4 = (float4*)xsh;
        float4* ssh4 = (float4*)ssh;
        const float4* gx4 = (const float4*)g_xd;
        const float4* gs4 = (const float4*)g_s;

        for (int sub = 0; sub < 4; sub++) {
            int n0 = base + sub * 64;
            __syncthreads();
#pragma unroll
            for (int i = 0; i < 8; i++)
                xsh4[t + i * 256] = gx4[(size_t)n0 * 32 + t + i * 256];
#pragma unroll
            for (int i = 0; i < 2; i++)
                ssh4[t + i * 256] = gs4[(size_t)n0 * 8 + t + i * 256];
            if (t < 64) dsh[t] = (float)g_odeg[n0 + t];
            __syncthreads();

            int nb = ns * 32;
#pragma unroll 2
            for (int n = nb; n < nb + 32; n++) {
                float4 xv = xsh4[n * 32 + fb];
                float4 sa = ssh4[n * 8 + kb * 2];
                float4 sb = ssh4[n * 8 + kb * 2 + 1];
                float sk[8] = {sa.x, sa.y, sa.z, sa.w, sb.x, sb.y, sb.z, sb.w};
                float xf[4] = {xv.x, xv.y, xv.z, xv.w};
#pragma unroll
                for (int i = 0; i < 8; i++)
#pragma unroll
                    for (int j = 0; j < 4; j++) acc[i][j] += sk[i] * xf[j];
            }

#pragma unroll 2
            for (int n = 0; n < 64; n++) {
                float4 s2 = ssh4[n * 8 + k2g];
                float s1v = ssh[n * 32 + k1];
                ssacc.x += s1v * s2.x; ssacc.y += s1v * s2.y;
                ssacc.z += s1v * s2.z; ssacc.w += s1v * s2.w;
            }
            if (t < 32) {
                for (int n = 0; n < 64; n++) {
                    float sv = ssh[n * 32 + t];
                    csacc += sv;
                    caacc += sv * dsh[n];
                }
            }
        }

        // write partials (no atomics): distinct slot per (chunk, ns)
        float* oa = g_outP + (size_t)((g * 8 + chunk) * 2 + ns) * (KC * HID);
        int k0 = kb * 8, f0 = fb * 4;
#pragma unroll
        for (int i = 0; i < 8; i++) {
            float4 v = make_float4(acc[i][0], acc[i][1], acc[i][2], acc[i][3]);
            *(float4*)&oa[(k0 + i) * HID + f0] = v;
        }
        *(float4*)&g_ssP[(size_t)(g * 8 + chunk) * 1024 + k1 * 32 + k2g * 4] = ssacc;
        if (t < 32) {
            g_csP[(g * 8 + chunk) * 32 + t] = csacc;
            g_caP[(g * 8 + chunk) * 32 + t] = caacc;
        }
    } else {
        // trace: 512 blocks, warp handles 8 consecutive rows; neighbors from fp16 s
        int b2 = blockIdx.x - 128;
        int wp = t >> 5, l = t & 31;
        int rbase = b2 * 64 + wp * 8;
        const __half* shp = g_sh;
        float tracc = 0.f;
        for (int r = 0; r < 8; r++) {
            int row = rbase + r;
            float sv = g_s[(size_t)row * KC + l];
            float acc = 0.f;
            int start = g_rowptr[row], cnt = g_indeg[row];
            for (int base = 0; base < cnt; base += 32) {
                int n = min(32, cnt - base);
                int idx_l = (base + l < cnt) ? g_csrsrc[start + base + l] : 0;
                int i = 0;
                for (; i + 8 <= n; i += 8) {
                    int sd[8]; __half hv[8];
#pragma unroll
                    for (int q = 0; q < 8; q++) sd[q] = __shfl_sync(0xffffffffu, idx_l, i + q);
#pragma unroll
                    for (int q = 0; q < 8; q++) hv[q] = shp[(size_t)sd[q] * KC + l];
#pragma unroll
                    for (int q = 0; q < 8; q++) acc += __half2float(hv[q]);
                }
                for (; i < n; i++) {
                    int s = __shfl_sync(0xffffffffu, idx_l, i);
                    acc += __half2float(shp[(size_t)s * KC + l]);
                }
            }
            tracc += acc * sv;
        }
#pragma unroll
        for (int o = 16; o; o >>= 1) tracc += __shfl_xor_sync(0xffffffffu, tracc, o);
        if (l == 0) atomicAdd(&g_tr[rbase >> 11], tracc);
    }
}

// blocks<512: log_softmax(selu(sum of outP partials)).  block 512: scalar loss.
__global__ void __launch_bounds__(128) final_k(float* __restrict__ outp) {
    int t = threadIdx.x;
    if (blockIdx.x < 512) {
        int r = blockIdx.x;          // r = g*32 + k
        int g = r >> 5, k = r & 31;
        __shared__ float shm[4], shs[4];
        float v = 0.f;
#pragma unroll
        for (int c = 0; c < 16; c++)
            v += g_outP[(size_t)(g * 16 + c) * (KC * HID) + k * HID + t];
        float y = selu_f(v);
        float mx = y;
#pragma unroll
        for (int o = 16; o; o >>= 1) mx = fmaxf(mx, __shfl_xor_sync(0xffffffffu, mx, o));
        if ((t & 31) == 0) shm[t >> 5] = mx;
        __syncthreads();
        float mall = fmaxf(fmaxf(shm[0], shm[1]), fmaxf(shm[2], shm[3]));
        float e = expf(y - mall);
        float sm = e;
#pragma unroll
        for (int o = 16; o; o >>= 1) sm += __shfl_xor_sync(0xffffffffu, sm, o);
        if ((t & 31) == 0) shs[t >> 5] = sm;
        __syncthreads();
        float tot = shs[0] + shs[1] + shs[2] + shs[3];
        outp[(size_t)r * HID + t] = y - mall - logf(tot);
    } else {
        __shared__ float parts[16];
        int wp = t >> 5, l = t & 31;
        for (int w = wp; w < 16; w += 4) {
            float dsum = 0.f;
            for (int n = l; n < NN; n += 32) dsum += (float)g_odeg[w * NN + n];
#pragma unroll
            for (int o = 16; o; o >>= 1) dsum += __shfl_xor_sync(0xffffffffu, dsum, o);
            float m = 0.5f * dsum;

            float ca = 0.f, cs = 0.f;
#pragma unroll
            for (int c = 0; c < 8; c++) {
                ca += g_caP[(w * 8 + c) * 32 + l];
                cs += g_csP[(w * 8 + c) * 32 + l];
            }
            float cn = ca * ca;
#pragma unroll
            for (int o = 16; o; o >>= 1) cn += __shfl_xor_sync(0xffffffffu, cn, o);
            float norm_tr = cn / (2.f * m);
            float spec = -(g_tr[w] - norm_tr) / (2.f * m);

            float sq = 0.f;
            for (int i = l; i < KC * KC; i += 32) {
                float v = 0.f;
#pragma unroll
                for (int c = 0; c < 8; c++) v += g_ssP[(size_t)(w * 8 + c) * 1024 + i];
                sq += v * v;
            }
#pragma unroll
            for (int o = 16; o; o >>= 1) sq += __shfl_xor_sync(0xffffffffu, sq, o);
            float fro = sqrtf(sq);
            float dtr = 0.f;
#pragma unroll
            for (int c = 0; c < 8; c++) dtr += g_ssP[(size_t)(w * 8 + c) * 1024 + l * 33];
#pragma unroll
            for (int o = 16; o; o >>= 1) dtr += __shfl_xor_sync(0xffffffffu, dtr, o);
            float ortho = sqrtf(fmaxf(2.f - 2.f * dtr / (fro * sqrtf((float)KC)), 0.f));

            float csn = cs * cs;
#pragma unroll
            for (int o = 16; o; o >>= 1) csn += __shfl_xor_sync(0xffffffffu, csn, o);
            float clus = sqrtf(csn) / (float)NN * sqrtf((float)KC) - 1.f;

            if (l == 0) parts[w] = spec + ortho + clus;
        }
        __syncthreads();
        if (t == 0) {
            float tot = 0.f;
#pragma unroll
            for (int i = 0; i < 16; i++) tot += parts[i];
            outp[NGB * KC * HID] = tot / (float)NGB;
        }
    }
}

// ---------------- launch ----------------
extern "C" void kernel_launch(void* const* d_in, const int* in_sizes, int n_in,
                              void* d_out, int out_size) {
    const float *x = 0, *gw = 0, *gb = 0, *gms = 0, *w1 = 0, *b1 = 0, *w2 = 0, *b2 = 0;
    const int *ei = 0;
    int n64 = 0;
    for (int i = 0; i < n_in; i++) {
        int sz = in_sizes[i];
        if (sz == NTT * CIN)       x = (const float*)d_in[i];
        else if (sz == 2 * EDG)    ei = (const int*)d_in[i];
        else if (sz == NTT)        { /* batch, unused (uniform graphs) */ }
        else if (sz == CIN) {
            if (n64 == 0) gw = (const float*)d_in[i];
            else if (n64 == 1) gb = (const float*)d_in[i];
            else gms = (const float*)d_in[i];
            n64++;
        }
        else if (sz == CIN * HID)  w1 = (const float*)d_in[i];
        else if (sz == HID)        b1 = (const float*)d_in[i];
        else if (sz == HID * KC)   w2 = (const float*)d_in[i];
        else if (sz == KC)         b2 = (const float*)d_in[i];
    }
    float* outp = (float*)d_out;
    float* s_out = outp + NGB * KC * HID + 1;   // s at offset 65537

    zero_k<<<64, 256>>>();
    stats_hist_k<<<128 + 1024, 512>>>(x, ei);
    prep2_k<<<NGB, 1024>>>(gw, gms);
    scatter_k<<<512, 256>>>(ei);
    gemm1h_k<<<512, 256>>>(x, gb, w1);
    gxsh_k<<<1024, 256>>>(b1, w2, b2, s_out);
    pool_trace_k<<<128 + 512, 256>>>();
    final_k<<<513, 128>>>(outp);
}

// round 17
// speedup vs baseline: 1.1963x; 1.1963x over previous
#include <cuda_runtime.h>
#include <cuda_fp16.h>
#include <math.h>

// Problem constants (fixed by the dataset)
#define NGB 16          // graphs
#define NN  2048        // nodes per graph
#define NTT 32768       // total nodes
#define CIN 64
#define HID 128
#define KC  32
#define EDG 524288      // total edges
#define EPG 32768       // edges per graph
#define GN_EPS 1e-5f
#define SELU_SCALE 1.0507009873554805f
#define SELU_ALPHA 1.6732632423543772f

// ---------------- scratch (device globals; no allocation allowed) ----------------
__device__ __align__(16) float g_sumP[128 * CIN];    // per (g,part) partial sums
__device__ __align__(16) float g_sumsqP[128 * CIN];
__device__ __align__(16) float g_gnA[NGB * CIN];     // alpha*mean
__device__ __align__(16) float g_gnS[NGB * CIN];     // gw * rsqrt(var+eps)
__device__ int   g_indeg[NTT];
__device__ int   g_odeg[NTT];
__device__ int   g_rowptr[NTT];
__device__ int   g_cursor[NTT];
__device__ int   g_csrsrc[EDG];
__device__ __align__(16) float g_dinv[NTT];
__device__ __align__(16) __half g_hwh[NTT * HID];    // fp16: dinv*(graphnorm(x)@w1)
__device__ __align__(16) __half g_sh[NTT * KC];      // fp16 copy of s (for trace)
__device__ __align__(16) float g_xd[NTT * HID];
__device__ __align__(16) float g_s[NTT * KC];
__device__ float g_tr[NGB];
__device__ float g_ca[NGB * KC];
__device__ float g_cs[NGB * KC];
__device__ __align__(16) float g_ss[NGB * KC * KC];
__device__ __align__(16) float g_outacc[NGB * KC * HID];

__device__ __forceinline__ float selu_f(float v) {
    return v > 0.f ? SELU_SCALE * v : SELU_SCALE * SELU_ALPHA * (expf(v) - 1.f);
}

// ---------------- kernels ----------------

// zero the accumulators that receive atomics.  grid 128 x 256.
__global__ void __launch_bounds__(256) zero_k() {
    int i = blockIdx.x * 256 + threadIdx.x;          // 0..32767
    g_indeg[i] = 0;
    g_odeg[i] = 0;
    g_outacc[i] = 0.f;
    g_outacc[i + 32768] = 0.f;
    if (i < NGB * KC * KC) g_ss[i] = 0.f;
    if (i < NGB * KC) { g_ca[i] = 0.f; g_cs[i] = 0.f; }
    if (i < NGB) g_tr[i] = 0.f;
}

// blocks<128: GraphNorm moment partials (no atomics).  blocks>=128: degree hist.
__global__ void __launch_bounds__(512) stats_hist_k(const float* __restrict__ x,
                                                    const int* __restrict__ ei) {
    int b = blockIdx.x, t = threadIdx.x;
    if (b < 128) {
        int g = b >> 3, part = b & 7;
        int c = t & 63, rp = t >> 6;
        float s = 0.f, q = 0.f;
        const float* xb = x + (size_t)g * NN * CIN;
        int r0 = part * 256;
        for (int r = r0 + rp; r < r0 + 256; r += 8) {
            float v = xb[r * CIN + c];
            s += v; q += v * v;
        }
        __shared__ float sh[2][8][64];
        sh[0][rp][c] = s; sh[1][rp][c] = q;
        __syncthreads();
        if (t < 64) {
            float ss = 0.f, qq = 0.f;
#pragma unroll
            for (int i = 0; i < 8; i++) { ss += sh[0][i][t]; qq += sh[1][i][t]; }
            g_sumP[b * 64 + t] = ss;
            g_sumsqP[b * 64 + t] = qq;
        }
    } else {
        int e = (b - 128) * 512 + t;    // 1024 blocks x 512 = EDG
        atomicAdd(&g_indeg[ei[EDG + e]], 1);
        atomicAdd(&g_odeg[ei[e]], 1);
    }
}

// per-graph: finalize GN coefficients + exclusive scan of indeg -> rowptr/cursor/dinv
// grid = 16 blocks x 1024.
__global__ void __launch_bounds__(1024) prep2_k(const float* __restrict__ gw,
                                                const float* __restrict__ gms) {
    __shared__ int wsum[32];
    int g = blockIdx.x, t = threadIdx.x;

    if (t < 64) {
        float ss = 0.f, qq = 0.f;
#pragma unroll
        for (int p = 0; p < 8; p++) {
            ss += g_sumP[(g * 8 + p) * 64 + t];
            qq += g_sumsqP[(g * 8 + p) * 64 + t];
        }
        float mean = ss * (1.f / NN);
        float alpha = gms[t];
        float var = qq * (1.f / NN) - (2.f * alpha - alpha * alpha) * mean * mean;
        g_gnS[g * 64 + t] = gw[t] * rsqrtf(var + GN_EPS);
        g_gnA[g * 64 + t] = alpha * mean;
    }

    int n0 = g * NN + 2 * t;
    int v0 = g_indeg[n0], v1 = g_indeg[n0 + 1];
    int ps = v0 + v1;
    int lane = t & 31, wp = t >> 5;
    int xs = ps;
#pragma unroll
    for (int o = 1; o < 32; o <<= 1) {
        int y = __shfl_up_sync(0xffffffffu, xs, o);
        if (lane >= o) xs += y;
    }
    if (lane == 31) wsum[wp] = xs;
    __syncthreads();
    if (t < 32) {
        int v = wsum[t];
        int y = v;
#pragma unroll
        for (int o = 1; o < 32; o <<= 1) {
            int z = __shfl_up_sync(0xffffffffu, y, o);
            if (t >= o) y += z;
        }
        wsum[t] = y - v;
    }
    __syncthreads();
    int ex = wsum[wp] + xs - ps;
    int ebase = g * EPG;
    g_rowptr[n0] = ebase + ex;
    g_rowptr[n0 + 1] = ebase + ex + v0;
    g_cursor[n0] = ebase + ex;
    g_cursor[n0 + 1] = ebase + ex + v0;
    g_dinv[n0] = rsqrtf((float)v0 + 1.f);
    g_dinv[n0 + 1] = rsqrtf((float)v1 + 1.f);
}

// CSR scatter: slot = cursor[dst]++, csrsrc[slot] = src.  ILP-1, max parallelism.
__global__ void __launch_bounds__(256) csr_scatter_k(const int* __restrict__ ei) {
    int e = blockIdx.x * 256 + threadIdx.x;
    int src = ei[e], dst = ei[EDG + e];
    int pos = atomicAdd(&g_cursor[dst], 1);
    g_csrsrc[pos] = src;
}

// fused GraphNorm + GEMM1 -> fp16: g_hwh = dinv*(graphnorm(x)@w1)
// grid 1024 blocks of 128 threads, grid-stride over 2048 tiles of 16 rows.
__global__ void __launch_bounds__(128) gemm1h_k(
    const float* __restrict__ x, const float* __restrict__ gb,
    const float* __restrict__ w1)
{
    __shared__ float w1t[HID * (CIN + 4)];   // ~34 KB
    __shared__ float A[CIN], S[CIN], Bc[CIN];
    __shared__ float hsh[8][CIN];
    __shared__ float dvs[16];
    int t = threadIdx.x;
    for (int c = 0; c < CIN; c++)
        w1t[t * (CIN + 4) + c] = w1[c * HID + t];
    if (t < 64) Bc[t] = gb[t];

    for (int tile = blockIdx.x; tile < NTT / 16; tile += 1024) {
        int row0 = tile * 16;
        int g = row0 >> 11;
        __syncthreads();
        if (t < 64) { A[t] = g_gnA[g * 64 + t]; S[t] = g_gnS[g * 64 + t]; }
        if (t < 16) dvs[t] = g_dinv[row0 + t];
        __syncthreads();
        for (int p = 0; p < 2; p++) {
            int r0 = row0 + p * 8;
#pragma unroll
            for (int i = 0; i < 4; i++) {
                int idx = t + i * 128;
                int rr = idx >> 6, c = idx & 63;
                float v = x[(size_t)(r0 + rr) * CIN + c];
                hsh[rr][c] = (v - A[c]) * S[c] + Bc[c];
            }
            __syncthreads();
            float acc[8];
#pragma unroll
            for (int r = 0; r < 8; r++) acc[r] = 0.f;
#pragma unroll
            for (int c = 0; c < CIN; c += 4) {
                float4 w = *(const float4*)&w1t[t * (CIN + 4) + c];
#pragma unroll
                for (int r = 0; r < 8; r++) {
                    float4 h = *(const float4*)&hsh[r][c];
                    acc[r] += w.x * h.x + w.y * h.y + w.z * h.z + w.w * h.w;
                }
            }
#pragma unroll
            for (int r = 0; r < 8; r++)
                g_hwh[(size_t)(r0 + r) * HID + t] = __float2half(acc[r] * dvs[p * 8 + r]);
            __syncthreads();
        }
    }
}

__device__ __forceinline__ void acc_h4(float4& acc, uint2 u) {
    __half2 ha = *(__half2*)&u.x, hb = *(__half2*)&u.y;
    float2 f0 = __half22float2(ha), f1 = __half22float2(hb);
    acc.x += f0.x; acc.y += f0.y; acc.z += f1.x; acc.w += f1.y;
}

// fused CSR gather (fp16 rows, MLP 4) + SELU + softmax(xd @ w2 + b2).
// one warp per dst row; 1024 blocks x 8 warps, grid-stride (4 sweeps).
__global__ void __launch_bounds__(256) gxsh_k(
    const float* __restrict__ b1, const float* __restrict__ w2,
    const float* __restrict__ b2, float* __restrict__ s_out)
{
    __shared__ float w2t[KC * (HID + 4)];   // ~17 KB
    __shared__ float xds[8][HID];
    int t = threadIdx.x, wp = t >> 5, l = t & 31;
    for (int idx = t; idx < KC * HID; idx += 256) {
        int j = idx >> 5, ll = idx & 31;
        w2t[ll * (HID + 4) + j] = w2[idx];
    }
    __syncthreads();

    float4 bv = ((const float4*)b1)[l];
    float bz = b2[l];
    const uint2* hwp = (const uint2*)g_hwh;   // row stride = 32 uint2 (256B)

    for (int row = blockIdx.x * 8 + wp; row < NTT; row += 8192) {
        float dd = g_dinv[row];
        float4 acc = make_float4(0.f, 0.f, 0.f, 0.f);
        acc_h4(acc, hwp[(size_t)row * 32 + l]);      // self-loop term
        int start = g_rowptr[row], cnt = g_indeg[row];
        for (int base = 0; base < cnt; base += 32) {
            int n = min(32, cnt - base);
            int idx_l = (base + l < cnt) ? g_csrsrc[start + base + l] : 0;
            int i = 0;
            for (; i + 4 <= n; i += 4) {
                int s0 = __shfl_sync(0xffffffffu, idx_l, i);
                int s1 = __shfl_sync(0xffffffffu, idx_l, i + 1);
                int s2 = __shfl_sync(0xffffffffu, idx_l, i + 2);
                int s3 = __shfl_sync(0xffffffffu, idx_l, i + 3);
                uint2 u0 = hwp[(size_t)s0 * 32 + l];
                uint2 u1 = hwp[(size_t)s1 * 32 + l];
                uint2 u2 = hwp[(size_t)s2 * 32 + l];
                uint2 u3 = hwp[(size_t)s3 * 32 + l];
                acc_h4(acc, u0); acc_h4(acc, u1); acc_h4(acc, u2); acc_h4(acc, u3);
            }
            for (; i < n; i++) {
                int s = __shfl_sync(0xffffffffu, idx_l, i);
                acc_h4(acc, hwp[(size_t)s * 32 + l]);
            }
        }
        float4 xv;
        xv.x = selu_f(acc.x * dd + bv.x);
        xv.y = selu_f(acc.y * dd + bv.y);
        xv.z = selu_f(acc.z * dd + bv.z);
        xv.w = selu_f(acc.w * dd + bv.w);
        ((float4*)g_xd)[(size_t)row * 32 + l] = xv;
        *((float4*)&xds[wp][l * 4]) = xv;
        __syncwarp();

        float z = bz;
#pragma unroll
        for (int j = 0; j < HID; j += 4) {
            float4 xj = *(const float4*)&xds[wp][j];
            float4 wj = *(const float4*)&w2t[l * (HID + 4) + j];
            z += xj.x * wj.x + xj.y * wj.y + xj.z * wj.z + xj.w * wj.w;
        }
        float mx = z;
#pragma unroll
        for (int o = 16; o; o >>= 1) mx = fmaxf(mx, __shfl_xor_sync(0xffffffffu, mx, o));
        float ez = expf(z - mx);
        float sm = ez;
#pragma unroll
        for (int o = 16; o; o >>= 1) sm += __shfl_xor_sync(0xffffffffu, sm, o);
        float sv = ez / sm;
        s_out[(size_t)row * KC + l] = sv;
        g_s[(size_t)row * KC + l] = sv;
        g_sh[(size_t)row * KC + l] = __float2half(sv);
        __syncwarp();
    }
}

// blocks<128: register-tiled pooled reductions (atomics).  blocks>=128: CSR trace (fp16 s, MLP 4).
__global__ void __launch_bounds__(256) pool_trace_k() {
    __shared__ float xsh[64 * 128];   // 32 KB
    __shared__ float ssh[64 * 32];    // 8 KB
    __shared__ float dsh[64];
    int t = threadIdx.x;

    if (blockIdx.x < 128) {
        int g = blockIdx.x >> 3;
        int chunk = blockIdx.x & 7;
        int base = g * NN + chunk * 256;
        int ns = t >> 7;
        int tile = t & 127;
        int kb = tile >> 5;
        int fb = tile & 31;
        int k1 = t >> 3;
        int k2g = t & 7;

        float acc[8][4];
#pragma unroll
        for (int i = 0; i < 8; i++)
#pragma unroll
            for (int j = 0; j < 4; j++) acc[i][j] = 0.f;
        float4 ssacc = make_float4(0.f, 0.f, 0.f, 0.f);
        float caacc = 0.f, csacc = 0.f;

        float4* xsh4 = (float4*)xsh;
        float4* ssh4 = (float4*)ssh;
        const float4* gx4 = (const float4*)g_xd;
        const float4* gs4 = (const float4*)g_s;

        for (int sub = 0; sub < 4; sub++) {
            int n0 = base + sub * 64;
            __syncthreads();
#pragma unroll
            for (int i = 0; i < 8; i++)
                xsh4[t + i * 256] = gx4[(size_t)n0 * 32 + t + i * 256];
#pragma unroll
            for (int i = 0; i < 2; i++)
                ssh4[t + i * 256] = gs4[(size_t)n0 * 8 + t + i * 256];
            if (t < 64) dsh[t] = (float)g_odeg[n0 + t];
            __syncthreads();

            int nb = ns * 32;
#pragma unroll 2
            for (int n = nb; n < nb + 32; n++) {
                float4 xv = xsh4[n * 32 + fb];
                float4 sa = ssh4[n * 8 + kb * 2];
                float4 sb = ssh4[n * 8 + kb * 2 + 1];
                float sk[8] = {sa.x, sa.y, sa.z, sa.w, sb.x, sb.y, sb.z, sb.w};
                float xf[4] = {xv.x, xv.y, xv.z, xv.w};
#pragma unroll
                for (int i = 0; i < 8; i++)
#pragma unroll
                    for (int j = 0; j < 4; j++) acc[i][j] += sk[i] * xf[j];
            }

#pragma unroll 2
            for (int n = 0; n < 64; n++) {
                float4 s2 = ssh4[n * 8 + k2g];
                float s1v = ssh[n * 32 + k1];
                ssacc.x += s1v * s2.x; ssacc.y += s1v * s2.y;
                ssacc.z += s1v * s2.z; ssacc.w += s1v * s2.w;
            }
            if (t < 32) {
                for (int n = 0; n < 64; n++) {
                    float sv = ssh[n * 32 + t];
                    csacc += sv;
                    caacc += sv * dsh[n];
                }
            }
        }

        float* oa = g_outacc + (size_t)g * KC * HID;
        int k0 = kb * 8, f0 = fb * 4;
#pragma unroll
        for (int i = 0; i < 8; i++)
#pragma unroll
            for (int j = 0; j < 4; j++)
                atomicAdd(&oa[(k0 + i) * HID + f0 + j], acc[i][j]);
        float* sp = g_ss + g * KC * KC + k1 * KC + k2g * 4;
        atomicAdd(sp + 0, ssacc.x);
        atomicAdd(sp + 1, ssacc.y);
        atomicAdd(sp + 2, ssacc.z);
        atomicAdd(sp + 3, ssacc.w);
        if (t < 32) {
            atomicAdd(&g_cs[g * 32 + t], csacc);
            atomicAdd(&g_ca[g * 32 + t], caacc);
        }
    } else {
        // trace: 512 blocks, warp handles 8 consecutive rows; neighbors from fp16 s
        int b2 = blockIdx.x - 128;
        int wp = t >> 5, l = t & 31;
        int rbase = b2 * 64 + wp * 8;
        const __half* shp = g_sh;
        float tracc = 0.f;
        for (int r = 0; r < 8; r++) {
            int row = rbase + r;
            float sv = g_s[(size_t)row * KC + l];
            float acc = 0.f;
            int start = g_rowptr[row], cnt = g_indeg[row];
            for (int base = 0; base < cnt; base += 32) {
                int n = min(32, cnt - base);
                int idx_l = (base + l < cnt) ? g_csrsrc[start + base + l] : 0;
                int i = 0;
                for (; i + 4 <= n; i += 4) {
                    int s0 = __shfl_sync(0xffffffffu, idx_l, i);
                    int s1 = __shfl_sync(0xffffffffu, idx_l, i + 1);
                    int s2 = __shfl_sync(0xffffffffu, idx_l, i + 2);
                    int s3 = __shfl_sync(0xffffffffu, idx_l, i + 3);
                    float v0 = __half2float(shp[(size_t)s0 * KC + l]);
                    float v1 = __half2float(shp[(size_t)s1 * KC + l]);
                    float v2 = __half2float(shp[(size_t)s2 * KC + l]);
                    float v3 = __half2float(shp[(size_t)s3 * KC + l]);
                    acc += v0 + v1 + v2 + v3;
                }
                for (; i < n; i++) {
                    int s = __shfl_sync(0xffffffffu, idx_l, i);
                    acc += __half2float(shp[(size_t)s * KC + l]);
                }
            }
            tracc += acc * sv;
        }
#pragma unroll
        for (int o = 16; o; o >>= 1) tracc += __shfl_xor_sync(0xffffffffu, tracc, o);
        if (l == 0) atomicAdd(&g_tr[rbase >> 11], tracc);
    }
}

// blocks<512: log_softmax(selu(outacc)).  block 512: scalar loss.
__global__ void __launch_bounds__(128) final_k(float* __restrict__ outp) {
    int t = threadIdx.x;
    if (blockIdx.x < 512) {
        int r = blockIdx.x;
        __shared__ float shm[4], shs[4];
        float y = selu_f(g_outacc[(size_t)r * HID + t]);
        float mx = y;
#pragma unroll
        for (int o = 16; o; o >>= 1) mx = fmaxf(mx, __shfl_xor_sync(0xffffffffu, mx, o));
        if ((t & 31) == 0) shm[t >> 5] = mx;
        __syncthreads();
        float mall = fmaxf(fmaxf(shm[0], shm[1]), fmaxf(shm[2], shm[3]));
        float e = expf(y - mall);
        float sm = e;
#pragma unroll
        for (int o = 16; o; o >>= 1) sm += __shfl_xor_sync(0xffffffffu, sm, o);
        if ((t & 31) == 0) shs[t >> 5] = sm;
        __syncthreads();
        float tot = shs[0] + shs[1] + shs[2] + shs[3];
        outp[(size_t)r * HID + t] = y - mall - logf(tot);
    } else {
        __shared__ float parts[16];
        int wp = t >> 5, l = t & 31;
        for (int w = wp; w < 16; w += 4) {
            float dsum = 0.f;
            for (int n = l; n < NN; n += 32) dsum += (float)g_odeg[w * NN + n];
#pragma unroll
            for (int o = 16; o; o >>= 1) dsum += __shfl_xor_sync(0xffffffffu, dsum, o);
            float m = 0.5f * dsum;

            float ca = g_ca[w * 32 + l];
            float cn = ca * ca;
#pragma unroll
            for (int o = 16; o; o >>= 1) cn += __shfl_xor_sync(0xffffffffu, cn, o);
            float norm_tr = cn / (2.f * m);
            float spec = -(g_tr[w] - norm_tr) / (2.f * m);

            float sq = 0.f;
            for (int i = l; i < KC * KC; i += 32) { float v = g_ss[w * 1024 + i]; sq += v * v; }
#pragma unroll
            for (int o = 16; o; o >>= 1) sq += __shfl_xor_sync(0xffffffffu, sq, o);
            float fro = sqrtf(sq);
            float dtr = g_ss[w * 1024 + l * 33];
#pragma unroll
            for (int o = 16; o; o >>= 1) dtr += __shfl_xor_sync(0xffffffffu, dtr, o);
            float ortho = sqrtf(fmaxf(2.f - 2.f * dtr / (fro * sqrtf((float)KC)), 0.f));

            float cs = g_cs[w * 32 + l];
            float csn = cs * cs;
#pragma unroll
            for (int o = 16; o; o >>= 1) csn += __shfl_xor_sync(0xffffffffu, csn, o);
            float clus = sqrtf(csn) / (float)NN * sqrtf((float)KC) - 1.f;

            if (l == 0) parts[w] = spec + ortho + clus;
        }
        __syncthreads();
        if (t == 0) {
            float tot = 0.f;
#pragma unroll
            for (int i = 0; i < 16; i++) tot += parts[i];
            outp[NGB * KC * HID] = tot / (float)NGB;
        }
    }
}

// ---------------- launch ----------------
extern "C" void kernel_launch(void* const* d_in, const int* in_sizes, int n_in,
                              void* d_out, int out_size) {
    const float *x = 0, *gw = 0, *gb = 0, *gms = 0, *w1 = 0, *b1 = 0, *w2 = 0, *b2 = 0;
    const int *ei = 0;
    int n64 = 0;
    for (int i = 0; i < n_in; i++) {
        int sz = in_sizes[i];
        if (sz == NTT * CIN)       x = (const float*)d_in[i];
        else if (sz == 2 * EDG)    ei = (const int*)d_in[i];
        else if (sz == NTT)        { /* batch, unused (uniform graphs) */ }
        else if (sz == CIN) {
            if (n64 == 0) gw = (const float*)d_in[i];
            else if (n64 == 1) gb = (const float*)d_in[i];
            else gms = (const float*)d_in[i];
            n64++;
        }
        else if (sz == CIN * HID)  w1 = (const float*)d_in[i];
        else if (sz == HID)        b1 = (const float*)d_in[i];
        else if (sz == HID * KC)   w2 = (const float*)d_in[i];
        else if (sz == KC)         b2 = (const float*)d_in[i];
    }
    float* outp = (float*)d_out;
    float* s_out = outp + NGB * KC * HID + 1;   // s at offset 65537

    zero_k<<<128, 256>>>();
    stats_hist_k<<<128 + 1024, 512>>>(x, ei);
    prep2_k<<<NGB, 1024>>>(gw, gms);
    csr_scatter_k<<<EDG / 256, 256>>>(ei);
    gemm1h_k<<<1024, 128>>>(x, gb, w1);
    gxsh_k<<<1024, 256>>>(b1, w2, b2, s_out);
    pool_trace_k<<<128 + 512, 256>>>();
    final_k<<<513, 128>>>(outp);
}